// round 12
// baseline (speedup 1.0000x reference)
#include <cuda_runtime.h>

// NSLayer: out = X + (w0 A + ... + w6 A^7 + w7 I) X,  A = I - X X^T
// 262144 independent 8x8 fp32 matrices, ONE thread per matrix.
// R10 = R7 algebra (B=A^2 even/odd split) on a register diet for 3 CTAs/SM:
//   - A kept ONLY in row-pair form A2p (32 regs, not 72 broadcast)
//   - B built via packed dots over A's rows (A symmetric): 144 fma2
//   - final matvec o = u + A t in transposed form (t re-paired per column)
// fma2/thread = 1568, FFMA2 rt~2; 12 warps/SM for issue-slot occupancy.

static constexpr int MPB = 128;   // matrices per block == threads per block
static constexpr int MS  = 68;    // padded matrix stride in floats

typedef unsigned long long u64;

__device__ __forceinline__ u64 pack2(float lo, float hi) {
    u64 r; asm("mov.b64 %0, {%1, %2};" : "=l"(r) : "f"(lo), "f"(hi)); return r;
}
__device__ __forceinline__ void unpack2(u64 v, float& lo, float& hi) {
    asm("mov.b64 {%0, %1}, %2;" : "=f"(lo), "=f"(hi) : "l"(v));
}
__device__ __forceinline__ float hadd2(u64 v) {
    float lo, hi; asm("mov.b64 {%0, %1}, %2;" : "=f"(lo), "=f"(hi) : "l"(v));
    return lo + hi;
}
__device__ __forceinline__ u64 fma2(u64 a, u64 b, u64 c) {
    u64 d; asm("fma.rn.f32x2 %0, %1, %2, %3;" : "=l"(d) : "l"(a), "l"(b), "l"(c)); return d;
}
__device__ __forceinline__ u64 mul2(u64 a, u64 b) {
    u64 d; asm("mul.rn.f32x2 %0, %1, %2;" : "=l"(d) : "l"(a), "l"(b)); return d;
}

#define TRI(r, k) ((r) >= (k) ? ((r) * ((r) + 1) / 2 + (k)) : ((k) * ((k) + 1) / 2 + (r)))

__global__ __launch_bounds__(128, 3)
void nslayer_kernel(const float* __restrict__ x,
                    const float* __restrict__ weight,
                    float* __restrict__ out)
{
    __shared__ float s[MPB * MS];
    const int tid = threadIdx.x;
    const size_t base = (size_t)blockIdx.x * (MPB * 64);

    // ---- preload weights, pre-broadcast ----
    const float4 wA4 = __ldg(reinterpret_cast<const float4*>(weight));
    const float4 wB4 = __ldg(reinterpret_cast<const float4*>(weight) + 1);
    const u64 w0_2 = pack2(wA4.x, wA4.x);
    const u64 w1_2 = pack2(wA4.y, wA4.y);
    const u64 w2_2 = pack2(wA4.z, wA4.z);
    const u64 w3_2 = pack2(wA4.w, wA4.w);
    const u64 w4_2 = pack2(wB4.x, wB4.x);
    const u64 w5_2 = pack2(wB4.y, wB4.y);
    const u64 w6_2 = pack2(wB4.z, wB4.z);
    const float w7p1 = wB4.w + 1.0f;
    const u64 w7p1_2 = pack2(w7p1, w7p1);

    // ---- coalesced load: block's 32KB chunk -> padded smem ----
    const float4* gin = reinterpret_cast<const float4*>(x + base);
#pragma unroll
    for (int k = 0; k < 16; k++) {
        int l4 = tid + k * 128;
        float4 v = gin[l4];
        int l = l4 << 2, m = l >> 6, w = l & 63;
        *reinterpret_cast<float4*>(&s[m * MS + w]) = v;
    }
    __syncthreads();

    // ---- Gram: A = I - X X^T, scalar triangle Cs ----
    float Cs[36];
    {
        u64 X2[8][4];
#pragma unroll
        for (int r = 0; r < 8; r++) {
            ulonglong2 p0 = *reinterpret_cast<const ulonglong2*>(&s[tid * MS + r * 8]);
            ulonglong2 p1 = *reinterpret_cast<const ulonglong2*>(&s[tid * MS + r * 8 + 4]);
            X2[r][0] = p0.x; X2[r][1] = p0.y; X2[r][2] = p1.x; X2[r][3] = p1.y;
        }
#pragma unroll
        for (int r = 0; r < 8; r++)
#pragma unroll
            for (int c = 0; c <= r; c++) {
                u64 d2 = mul2(X2[r][0], X2[c][0]);
#pragma unroll
                for (int kp = 1; kp < 4; kp++) d2 = fma2(X2[r][kp], X2[c][kp], d2);
                Cs[TRI(r, c)] = ((r == c) ? 1.0f : 0.0f) - hadd2(d2);
            }
    }   // X2 dies

    // ---- A in row-pair form (32 regs): A2p[r][kp] = {A[r][2kp], A[r][2kp+1]} ----
    u64 A2p[8][4];
#pragma unroll
    for (int r = 0; r < 8; r++)
#pragma unroll
        for (int kp = 0; kp < 4; kp++)
            A2p[r][kp] = pack2(Cs[TRI(r, 2 * kp)], Cs[TRI(r, 2 * kp + 1)]);

    // ---- B = A*A triangle via packed dots (A symmetric), broadcast form ----
    u64 B2b[36];
#pragma unroll
    for (int r = 0; r < 8; r++)
#pragma unroll
        for (int c = 0; c <= r; c++) {
            u64 d2 = mul2(A2p[r][0], A2p[c][0]);
#pragma unroll
            for (int kp = 1; kp < 4; kp++) d2 = fma2(A2p[r][kp], A2p[c][kp], d2);
            float v = hadd2(d2);
            B2b[TRI(r, c)] = pack2(v, v);
        }
    // Cs dies here. Persistent: B2b(72) + A2p(32) + weights(16).

    // ---- per column-pair: V=BX, W=BV, Z=BW; t,u folds; o = u + A t ----
#pragma unroll
    for (int cp = 0; cp < 4; cp++) {
        u64 xv[8], t[8], u[8], v[8];
#pragma unroll
        for (int k = 0; k < 8; k++)
            xv[k] = *reinterpret_cast<const u64*>(&s[tid * MS + k * 8 + 2 * cp]);
        // v = B x
#pragma unroll
        for (int r = 0; r < 8; r++) {
            u64 d2 = mul2(B2b[TRI(r, 0)], xv[0]);
#pragma unroll
            for (int k = 1; k < 8; k++) d2 = fma2(B2b[TRI(r, k)], xv[k], d2);
            v[r] = d2;
        }
#pragma unroll
        for (int r = 0; r < 8; r++) {
            t[r] = fma2(w2_2, v[r], mul2(w0_2, xv[r]));
            u[r] = fma2(w1_2, v[r], mul2(w7p1_2, xv[r]));
        }
        // w = B v (into xv)
#pragma unroll
        for (int r = 0; r < 8; r++) {
            u64 d2 = mul2(B2b[TRI(r, 0)], v[0]);
#pragma unroll
            for (int k = 1; k < 8; k++) d2 = fma2(B2b[TRI(r, k)], v[k], d2);
            xv[r] = d2;
        }
#pragma unroll
        for (int r = 0; r < 8; r++) {
            t[r] = fma2(w4_2, xv[r], t[r]);
            u[r] = fma2(w3_2, xv[r], u[r]);
        }
        // z = B w (into v)
#pragma unroll
        for (int r = 0; r < 8; r++) {
            u64 d2 = mul2(B2b[TRI(r, 0)], xv[0]);
#pragma unroll
            for (int k = 1; k < 8; k++) d2 = fma2(B2b[TRI(r, k)], xv[k], d2);
            v[r] = d2;
        }
#pragma unroll
        for (int r = 0; r < 8; r++) {
            t[r] = fma2(w6_2, v[r], t[r]);
            u[r] = fma2(w5_2, v[r], u[r]);
        }

        // ---- o = u + A t, transposed: re-pair t per column along k ----
        {
            float tl[8], th[8];
#pragma unroll
            for (int r = 0; r < 8; r++) unpack2(t[r], tl[r], th[r]);
            u64 tc0[4], tc1[4];
#pragma unroll
            for (int kp = 0; kp < 4; kp++) {
                tc0[kp] = pack2(tl[2 * kp], tl[2 * kp + 1]);
                tc1[kp] = pack2(th[2 * kp], th[2 * kp + 1]);
            }
#pragma unroll
            for (int r = 0; r < 8; r++) {
                u64 d0 = mul2(A2p[r][0], tc0[0]);
                u64 d1 = mul2(A2p[r][0], tc1[0]);
#pragma unroll
                for (int kp = 1; kp < 4; kp++) {
                    d0 = fma2(A2p[r][kp], tc0[kp], d0);
                    d1 = fma2(A2p[r][kp], tc1[kp], d1);
                }
                float ul, uh; unpack2(u[r], ul, uh);
                float o0 = ul + hadd2(d0);
                float o1 = uh + hadd2(d1);
                *reinterpret_cast<u64*>(&s[tid * MS + r * 8 + 2 * cp]) = pack2(o0, o1);
            }
        }
    }
    __syncthreads();

    // ---- coalesced store: padded smem -> block's 32KB output chunk ----
    float4* gout = reinterpret_cast<float4*>(out + base);
#pragma unroll
    for (int k = 0; k < 16; k++) {
        int l4 = tid + k * 128;
        int l = l4 << 2, m = l >> 6, w = l & 63;
        gout[l4] = *reinterpret_cast<const float4*>(&s[m * MS + w]);
    }
}

extern "C" void kernel_launch(void* const* d_in, const int* in_sizes, int n_in,
                              void* d_out, int out_size) {
    const float* x = (const float*)d_in[0];
    const float* w = (const float*)d_in[1];
    float* out = (float*)d_out;
    int nmat = in_sizes[0] / 64;          // 262144
    int blocks = nmat / MPB;              // 2048 (exact)
    nslayer_kernel<<<blocks, MPB>>>(x, w, out);
}

// round 13
// speedup vs baseline: 1.2144x; 1.2144x over previous
#include <cuda_runtime.h>

// NSLayer: out = X + (w0 A + ... + w6 A^7 + w7 I) X,  A = I - X X^T
// 262144 independent 8x8 fp32 matrices, ONE thread per matrix.
// R11 = R7 structure (B=A^2 even/odd split, broadcast-only fma chains) with:
//   - B built via packed dots over A's rows (A symmetric): 288 -> 144 fma2
//   - 64-thread blocks, 4 CTAs/SM: finer waves, phase overlap across CTAs
// fma2/thread = 1568 @ FFMA2 rt=3 (RF-bank floor).

static constexpr int MPB = 64;    // matrices per block == threads per block
static constexpr int MS  = 68;    // padded matrix stride in floats

typedef unsigned long long u64;

__device__ __forceinline__ u64 pack2(float lo, float hi) {
    u64 r; asm("mov.b64 %0, {%1, %2};" : "=l"(r) : "f"(lo), "f"(hi)); return r;
}
__device__ __forceinline__ float hadd2(u64 v) {
    float lo, hi; asm("mov.b64 {%0, %1}, %2;" : "=f"(lo), "=f"(hi) : "l"(v));
    return lo + hi;
}
__device__ __forceinline__ u64 fma2(u64 a, u64 b, u64 c) {
    u64 d; asm("fma.rn.f32x2 %0, %1, %2, %3;" : "=l"(d) : "l"(a), "l"(b), "l"(c)); return d;
}
__device__ __forceinline__ u64 mul2(u64 a, u64 b) {
    u64 d; asm("mul.rn.f32x2 %0, %1, %2;" : "=l"(d) : "l"(a), "l"(b)); return d;
}

#define TRI(r, k) ((r) >= (k) ? ((r) * ((r) + 1) / 2 + (k)) : ((k) * ((k) + 1) / 2 + (r)))

__global__ __launch_bounds__(MPB, 4)
void nslayer_kernel(const float* __restrict__ x,
                    const float* __restrict__ weight,
                    float* __restrict__ out)
{
    __shared__ float s[MPB * MS];
    const int tid = threadIdx.x;
    const size_t base = (size_t)blockIdx.x * (MPB * 64);

    // ---- preload weights, pre-broadcast ----
    const float4 wA4 = __ldg(reinterpret_cast<const float4*>(weight));
    const float4 wB4 = __ldg(reinterpret_cast<const float4*>(weight) + 1);
    const u64 w0_2 = pack2(wA4.x, wA4.x);
    const u64 w1_2 = pack2(wA4.y, wA4.y);
    const u64 w2_2 = pack2(wA4.z, wA4.z);
    const u64 w3_2 = pack2(wA4.w, wA4.w);
    const u64 w4_2 = pack2(wB4.x, wB4.x);
    const u64 w5_2 = pack2(wB4.y, wB4.y);
    const u64 w6_2 = pack2(wB4.z, wB4.z);
    const float w7p1 = wB4.w + 1.0f;
    const u64 w7p1_2 = pack2(w7p1, w7p1);

    // ---- coalesced load: block's 16KB chunk -> padded smem ----
    const float4* gin = reinterpret_cast<const float4*>(x + base);
#pragma unroll
    for (int k = 0; k < 16; k++) {
        int l4 = tid + k * MPB;
        float4 v = gin[l4];
        int l = l4 << 2, m = l >> 6, w = l & 63;
        *reinterpret_cast<float4*>(&s[m * MS + w]) = v;
    }
    __syncthreads();

    // ---- Gram: A = I - X X^T, scalar triangle Cs (packed row dots) ----
    float Cs[36];
    {
        u64 X2[8][4];
#pragma unroll
        for (int r = 0; r < 8; r++) {
            ulonglong2 p0 = *reinterpret_cast<const ulonglong2*>(&s[tid * MS + r * 8]);
            ulonglong2 p1 = *reinterpret_cast<const ulonglong2*>(&s[tid * MS + r * 8 + 4]);
            X2[r][0] = p0.x; X2[r][1] = p0.y; X2[r][2] = p1.x; X2[r][3] = p1.y;
        }
#pragma unroll
        for (int r = 0; r < 8; r++)
#pragma unroll
            for (int c = 0; c <= r; c++) {
                u64 d2 = mul2(X2[r][0], X2[c][0]);
#pragma unroll
                for (int kp = 1; kp < 4; kp++) d2 = fma2(X2[r][kp], X2[c][kp], d2);
                Cs[TRI(r, c)] = ((r == c) ? 1.0f : 0.0f) - hadd2(d2);
            }
    }   // X2 dies

    // ---- B = A*A triangle via packed dots over A's rows (A symmetric);
    //      result packed to broadcast form for the chains ----
    u64 B2b[36];
    {
        u64 A2p[8][4];
#pragma unroll
        for (int r = 0; r < 8; r++)
#pragma unroll
            for (int kp = 0; kp < 4; kp++)
                A2p[r][kp] = pack2(Cs[TRI(r, 2 * kp)], Cs[TRI(r, 2 * kp + 1)]);
#pragma unroll
        for (int r = 0; r < 8; r++)
#pragma unroll
            for (int c = 0; c <= r; c++) {
                u64 d2 = mul2(A2p[r][0], A2p[c][0]);
#pragma unroll
                for (int kp = 1; kp < 4; kp++) d2 = fma2(A2p[r][kp], A2p[c][kp], d2);
                float v = hadd2(d2);
                B2b[TRI(r, c)] = pack2(v, v);
            }
    }   // A2p dies

    // ---- A broadcast form for the final matvec (alu-free in chains) ----
    u64 A2b[36];
#pragma unroll
    for (int e = 0; e < 36; e++) A2b[e] = pack2(Cs[e], Cs[e]);
    // Cs dies

    // ---- per column-pair: V=BX, W=BV, Z=BW; t,u folds; o = u + A t ----
#pragma unroll
    for (int cp = 0; cp < 4; cp++) {
        u64 xv[8], t[8], u[8], v[8];
#pragma unroll
        for (int k = 0; k < 8; k++)
            xv[k] = *reinterpret_cast<const u64*>(&s[tid * MS + k * 8 + 2 * cp]);
        // v = B x
#pragma unroll
        for (int r = 0; r < 8; r++) {
            u64 d2 = mul2(B2b[TRI(r, 0)], xv[0]);
#pragma unroll
            for (int k = 1; k < 8; k++) d2 = fma2(B2b[TRI(r, k)], xv[k], d2);
            v[r] = d2;
        }
#pragma unroll
        for (int r = 0; r < 8; r++) {
            t[r] = fma2(w2_2, v[r], mul2(w0_2, xv[r]));
            u[r] = fma2(w1_2, v[r], mul2(w7p1_2, xv[r]));
        }
        // w = B v (into xv)
#pragma unroll
        for (int r = 0; r < 8; r++) {
            u64 d2 = mul2(B2b[TRI(r, 0)], v[0]);
#pragma unroll
            for (int k = 1; k < 8; k++) d2 = fma2(B2b[TRI(r, k)], v[k], d2);
            xv[r] = d2;
        }
#pragma unroll
        for (int r = 0; r < 8; r++) {
            t[r] = fma2(w4_2, xv[r], t[r]);
            u[r] = fma2(w3_2, xv[r], u[r]);
        }
        // z = B w (into v)
#pragma unroll
        for (int r = 0; r < 8; r++) {
            u64 d2 = mul2(B2b[TRI(r, 0)], xv[0]);
#pragma unroll
            for (int k = 1; k < 8; k++) d2 = fma2(B2b[TRI(r, k)], xv[k], d2);
            v[r] = d2;
        }
#pragma unroll
        for (int r = 0; r < 8; r++) {
            t[r] = fma2(w6_2, v[r], t[r]);
            u[r] = fma2(w5_2, v[r], u[r]);
        }
        // o = u + A t, store this column pair
#pragma unroll
        for (int r = 0; r < 8; r++) {
            u64 d2 = u[r];
#pragma unroll
            for (int k = 0; k < 8; k++) d2 = fma2(A2b[TRI(r, k)], t[k], d2);
            *reinterpret_cast<u64*>(&s[tid * MS + r * 8 + 2 * cp]) = d2;
        }
    }
    __syncthreads();

    // ---- coalesced store: padded smem -> block's 16KB output chunk ----
    float4* gout = reinterpret_cast<float4*>(out + base);
#pragma unroll
    for (int k = 0; k < 16; k++) {
        int l4 = tid + k * MPB;
        int l = l4 << 2, m = l >> 6, w = l & 63;
        gout[l4] = *reinterpret_cast<const float4*>(&s[m * MS + w]);
    }
}

extern "C" void kernel_launch(void* const* d_in, const int* in_sizes, int n_in,
                              void* d_out, int out_size) {
    const float* x = (const float*)d_in[0];
    const float* w = (const float*)d_in[1];
    float* out = (float*)d_out;
    int nmat = in_sizes[0] / 64;          // 262144
    int blocks = nmat / MPB;              // 4096 (exact)
    nslayer_kernel<<<blocks, MPB>>>(x, w, out);
}